// round 10
// baseline (speedup 1.0000x reference)
#include <cuda_runtime.h>

#define B_ 8
#define C_ 64
#define H_ 256
#define W_ 256
#define E_ 256
#define NH_ 8
#define HD_ 32
#define NPIX (H_*W_)

#define CHB 1024                 // 64-px chunks per batch image
#define PST 68                   // floats per (chunk,head) partial: S[64], m, T, PJ, pad

// per-warp smem unit (floats): xs[64*64] | w8[64*16] | la[64*8]
#define XS_F (64*64)
#define W8_F (64*16)
#define LA_F (64*8)
#define UNIT_F (XS_F + W8_F + LA_F)      // 5632 floats = 22528 B
#define SMEM_MAIN_B (2*UNIT_F*4)         // 45056 B per 2-warp block

__device__ float g_wa[B_*NH_*C_];
__device__ float g_wb[B_*NH_*C_];
__device__ float g_wc[B_*NH_*C_];
__device__ float g_s [B_*NH_*3];
__device__ float g_part[(size_t)B_*CHB*NH_*PST];   // 17.8 MB scratch

#define FMA2(a, x, w) asm("fma.rn.f32x2 %0, %1, %2, %0;" : "+l"(a) : "l"(x), "l"(w))

// ---------------------------------------------------------------------------
// Prep: per (b,h) build wa/wb/wc[64] and scalars. Stage-2 weights prefetched
// before stage-1's dependent chain.
// ---------------------------------------------------------------------------
__global__ void prep_kernel(const float* __restrict__ z,  const float* __restrict__ pos,
                            const float* __restrict__ Wq, const float* __restrict__ bq,
                            const float* __restrict__ Wk, const float* __restrict__ bk,
                            const float* __restrict__ Wp, const float* __restrict__ bp)
{
    int b = blockIdx.x >> 3, h = blockIdx.x & 7;
    __shared__ float tA[HD_], tB[HD_], tC[HD_];
    int tid = threadIdx.x;
    const float s = 0.1767766952966369f;  // 1/sqrt(32)

    // prefetch stage-2 weights (independent of stage 1)
    int c2 = tid >> 2, sub = tid & 3;
    float wkr[8];
    #pragma unroll
    for (int d = 0; d < 8; d++)
        wkr[d] = __ldg(Wk + (h*HD_ + sub*8 + d)*C_ + c2);

    // stage 1: qv[d], 8 threads per d
    {
        int d = tid >> 3, q = tid & 7;
        int e = h*HD_ + d;
        const float4* zr = reinterpret_cast<const float4*>(z + b*C_);
        const float4* wq = reinterpret_cast<const float4*>(Wq + e*C_);
        float4 z0 = zr[q*2], z1 = zr[q*2+1];
        float4 w0 = __ldg(wq + q*2), w1 = __ldg(wq + q*2 + 1);
        float qv = z0.x*w0.x + z0.y*w0.y + z0.z*w0.z + z0.w*w0.w
                 + z1.x*w1.x + z1.y*w1.y + z1.z*w1.z + z1.w*w1.w;
        qv += __shfl_xor_sync(0xffffffffu, qv, 1);
        qv += __shfl_xor_sync(0xffffffffu, qv, 2);
        qv += __shfl_xor_sync(0xffffffffu, qv, 4);
        if (q == 0) {
            qv += bq[e];
            float wp0 = Wp[2*d], wp1 = Wp[2*d+1];
            float p0 = pos[(b*NH_+h)*2], p1 = pos[(b*NH_+h)*2+1];
            float cc = bp[d] - wp0*p0 - wp1*p1;
            tA[d] = qv*wp0*s; tB[d] = qv*wp1*s; tC[d] = qv*cc*s;
        }
    }
    __syncthreads();
    // stage 2: project through Wk (prefetched)
    {
        float a = 0.f, bb = 0.f, cc = 0.f;
        #pragma unroll
        for (int d = 0; d < 8; d++) {
            int dd = sub*8 + d;
            float w = wkr[d];
            a += tA[dd]*w; bb += tB[dd]*w; cc += tC[dd]*w;
        }
        a  += __shfl_xor_sync(0xffffffffu, a, 1);
        bb += __shfl_xor_sync(0xffffffffu, bb, 1);
        cc += __shfl_xor_sync(0xffffffffu, cc, 1);
        a  += __shfl_xor_sync(0xffffffffu, a, 2);
        bb += __shfl_xor_sync(0xffffffffu, bb, 2);
        cc += __shfl_xor_sync(0xffffffffu, cc, 2);
        if (sub == 0) {
            int base = (b*NH_+h)*C_;
            g_wa[base+c2] = a; g_wb[base+c2] = bb; g_wc[base+c2] = cc;
        }
    }
    if (tid < 3) {
        const float* t = (tid==0) ? tA : ((tid==1) ? tB : tC);
        float sv = 0.f;
        #pragma unroll
        for (int d = 0; d < HD_; d++) sv += t[d]*bk[h*NH_*4 + d];  // h*HD_
        g_s[(b*NH_+h)*3 + tid] = sv;
    }
}

// ---------------------------------------------------------------------------
// Main: warp-autonomous. Each warp owns a 64-px chunk; NO __syncthreads.
// xs swizzle: word(p,c) = p*64 + ((c + 8*(p&3) + (p>>2)) & 63)
//   conflict-free for staging stores (px 2l,2l+1), phase-A reads (p=l,l+32),
//   phase-B reads (c=l,l+32).
// ---------------------------------------------------------------------------
__global__ void __launch_bounds__(64, 5) main_kernel(const float* __restrict__ x)
{
    extern __shared__ float sm[];
    int tid = threadIdx.x;
    int wid = tid >> 5, l = tid & 31;
    float* xs = sm + wid*UNIT_F;
    float* w8 = xs + XS_F;
    float* la = w8 + W8_F;

    int b = blockIdx.y;
    int chunk = blockIdx.x*2 + wid;
    int row = chunk >> 2, quarter = chunk & 3;
    float rowf = (float)row;

    // srow/sbv per head via shfl (lanes 0-7 compute)
    float sr = 0.f, sb = 0.f;
    if (l < 8) {
        const float* gs = g_s + (b*NH_ + l)*3;
        sr = gs[2] + rowf*gs[0];
        sb = gs[1];
    }
    float srowr[8], sbvr[8];
    #pragma unroll
    for (int h = 0; h < 8; h++) {
        srowr[h] = __shfl_sync(0xffffffffu, sr, h);
        sbvr[h]  = __shfl_sync(0xffffffffu, sb, h);
    }

    // ---- stage x: per channel LDG.64 (2 px/lane), swizzled STS
    {
        const float* xg = x + (size_t)b*C_*NPIX + (size_t)row*W_ + quarter*64;
        int p0 = 2*l, p1 = 2*l + 1;
        int u0 = (8*(p0&3) + (p0>>2));
        int u1 = (8*(p1&3) + (p1>>2));
        float* d0 = xs + p0*64;
        float* d1 = xs + p1*64;
        #pragma unroll
        for (int rnd = 0; rnd < 4; rnd++) {
            float2 v[16];
            #pragma unroll
            for (int j = 0; j < 16; j++) {
                int c = rnd*16 + j;
                v[j] = __ldg(reinterpret_cast<const float2*>(xg + (size_t)c*NPIX) + l);
            }
            #pragma unroll
            for (int j = 0; j < 16; j++) {
                int c = rnd*16 + j;
                d0[(c + u0) & 63] = v[j].x;
                d1[(c + u1) & 63] = v[j].y;
            }
        }
    }

    // ---- w8 fill: coalesced/conflict-free, word idx = l + 32k
    #pragma unroll 8
    for (int k = 0; k < 32; k++) {
        int idx = l + 32*k;
        int c = idx >> 4, s2 = idx & 15, h = s2 >> 1;
        int gi = (b*NH_ + h)*C_ + c;
        float val;
        if (s2 & 1) val = g_wb[gi];
        else        val = g_wc[gi] + rowf*g_wa[gi];
        w8[idx] = val;
    }
    __syncwarp();

    // ---- Phase A: logits, pixels p0=l, p1=l+32
    int p0 = l, p1 = l + 32;
    float lg0[8], lg1[8];
    {
        unsigned long long acc0[8], acc1[8];
        #pragma unroll
        for (int h = 0; h < 8; h++) { acc0[h] = 0ULL; acc1[h] = 0ULL; }
        const float* xr0 = xs + p0*64;
        const float* xr1 = xs + p1*64;
        int G0 = 8*(p0&3) + (p0>>2);
        int G1 = 8*(p1&3) + (p1>>2);
        #pragma unroll 4
        for (int c = 0; c < 64; c++) {
            float x0 = xr0[(c + G0) & 63];
            float x1 = xr1[(c + G1) & 63];
            unsigned long long xx0, xx1;
            asm("mov.b64 %0, {%1, %1};" : "=l"(xx0) : "f"(x0));
            asm("mov.b64 %0, {%1, %1};" : "=l"(xx1) : "f"(x1));
            const ulonglong2* wp = reinterpret_cast<const ulonglong2*>(w8 + c*16);
            ulonglong2 wA = wp[0], wB = wp[1];
            FMA2(acc0[0], xx0, wA.x);  FMA2(acc1[0], xx1, wA.x);
            FMA2(acc0[1], xx0, wA.y);  FMA2(acc1[1], xx1, wA.y);
            FMA2(acc0[2], xx0, wB.x);  FMA2(acc1[2], xx1, wB.x);
            FMA2(acc0[3], xx0, wB.y);  FMA2(acc1[3], xx1, wB.y);
            ulonglong2 wC = wp[2], wD = wp[3];
            FMA2(acc0[4], xx0, wC.x);  FMA2(acc1[4], xx1, wC.x);
            FMA2(acc0[5], xx0, wC.y);  FMA2(acc1[5], xx1, wC.y);
            FMA2(acc0[6], xx0, wD.x);  FMA2(acc1[6], xx1, wD.x);
            FMA2(acc0[7], xx0, wD.y);  FMA2(acc1[7], xx1, wD.y);
        }
        float cf0 = (float)(quarter*64 + p0);
        float cf1 = (float)(quarter*64 + p1);
        #pragma unroll
        for (int h = 0; h < 8; h++) {
            float r, bb;
            asm("mov.b64 {%0, %1}, %2;" : "=f"(r), "=f"(bb) : "l"(acc0[h]));
            lg0[h] = (r + srowr[h]) + cf0*(bb + sbvr[h]);
            asm("mov.b64 {%0, %1}, %2;" : "=f"(r), "=f"(bb) : "l"(acc1[h]));
            lg1[h] = (r + srowr[h]) + cf1*(bb + sbvr[h]);
        }
    }

    // ---- warp-local softmax partials
    {
        float mh[8], e0[8], e1[8], th[8], pjh[8];
        #pragma unroll
        for (int h = 0; h < 8; h++) mh[h] = fmaxf(lg0[h], lg1[h]);
        #pragma unroll
        for (int o = 16; o; o >>= 1) {
            #pragma unroll
            for (int h = 0; h < 8; h++)
                mh[h] = fmaxf(mh[h], __shfl_xor_sync(0xffffffffu, mh[h], o));
        }
        float cf0 = (float)(quarter*64 + p0);
        float cf1 = (float)(quarter*64 + p1);
        #pragma unroll
        for (int h = 0; h < 8; h++) {
            e0[h] = __expf(lg0[h] - mh[h]);
            e1[h] = __expf(lg1[h] - mh[h]);
            th[h]  = e0[h] + e1[h];
            pjh[h] = e0[h]*cf0 + e1[h]*cf1;
        }
        *reinterpret_cast<float4*>(la + p0*8)     = make_float4(e0[0], e0[1], e0[2], e0[3]);
        *reinterpret_cast<float4*>(la + p0*8 + 4) = make_float4(e0[4], e0[5], e0[6], e0[7]);
        *reinterpret_cast<float4*>(la + p1*8)     = make_float4(e1[0], e1[1], e1[2], e1[3]);
        *reinterpret_cast<float4*>(la + p1*8 + 4) = make_float4(e1[4], e1[5], e1[6], e1[7]);
        #pragma unroll
        for (int o = 16; o; o >>= 1) {
            #pragma unroll
            for (int h = 0; h < 8; h++) {
                th[h]  += __shfl_xor_sync(0xffffffffu, th[h],  o);
                pjh[h] += __shfl_xor_sync(0xffffffffu, pjh[h], o);
            }
        }
        size_t cb = ((size_t)(b*CHB + chunk)*NH_);
        #pragma unroll
        for (int h = 0; h < 8; h++) {
            if (l == h) {
                float* pb = g_part + (cb + h)*PST;
                pb[64] = mh[h]; pb[65] = th[h]; pb[66] = pjh[h];
            }
        }
        __syncwarp();
    }

    // ---- Phase B: S[h][c] for c0=l, c1=l+32 over 64 px; head-pair FMA2
    {
        int c0 = l, c1 = l + 32;
        unsigned long long acc[8];
        #pragma unroll
        for (int j = 0; j < 8; j++) acc[j] = 0ULL;
        #pragma unroll 4
        for (int p = 0; p < 64; p++) {
            int up = 8*(p&3) + (p>>2);
            float xv0 = xs[p*64 + ((c0 + up) & 63)];
            float xv1 = xs[p*64 + ((c1 + up) & 63)];
            unsigned long long xx0, xx1;
            asm("mov.b64 %0, {%1, %1};" : "=l"(xx0) : "f"(xv0));
            asm("mov.b64 %0, {%1, %1};" : "=l"(xx1) : "f"(xv1));
            ulonglong2 eA = *reinterpret_cast<const ulonglong2*>(la + p*8);
            ulonglong2 eB = *reinterpret_cast<const ulonglong2*>(la + p*8 + 4);
            FMA2(acc[0], xx0, eA.x);  FMA2(acc[4], xx1, eA.x);
            FMA2(acc[1], xx0, eA.y);  FMA2(acc[5], xx1, eA.y);
            FMA2(acc[2], xx0, eB.x);  FMA2(acc[6], xx1, eB.x);
            FMA2(acc[3], xx0, eB.y);  FMA2(acc[7], xx1, eB.y);
        }
        size_t cb = ((size_t)(b*CHB + chunk)*NH_);
        #pragma unroll
        for (int j = 0; j < 4; j++) {
            float sa, sbf, sc, sd;
            asm("mov.b64 {%0, %1}, %2;" : "=f"(sa), "=f"(sbf) : "l"(acc[j]));
            asm("mov.b64 {%0, %1}, %2;" : "=f"(sc), "=f"(sd) : "l"(acc[j+4]));
            g_part[(cb + 2*j    )*PST + c0] = sa;
            g_part[(cb + 2*j + 1)*PST + c0] = sbf;
            g_part[(cb + 2*j    )*PST + c1] = sc;
            g_part[(cb + 2*j + 1)*PST + c1] = sd;
        }
    }
}

// ---------------------------------------------------------------------------
// Combine: per (b,h), 512 threads merge 1024 chunk-partials (L2-resident).
// ---------------------------------------------------------------------------
__global__ void __launch_bounds__(512) combine_kernel(const float* __restrict__ Wv,
                                                      const float* __restrict__ bv,
                                                      float* __restrict__ out)
{
    int b = blockIdx.x >> 3, h = blockIdx.x & 7;
    __shared__ float fsh[CHB], Ssh[64], Sp[8][64];
    __shared__ float wred[16], wsum[16][3];
    __shared__ float Msh;
    int tid = threadIdx.x, warp = tid >> 5, lane = tid & 31;

    size_t base = (size_t)b*CHB*NH_;
    const float* pb0 = g_part + (base + (size_t)tid*NH_ + h)*PST;
    const float* pb1 = g_part + (base + (size_t)(tid+512)*NH_ + h)*PST;
    float m0 = pb0[64], T0 = pb0[65], PJ0 = pb0[66];
    float m1 = pb1[64], T1 = pb1[65], PJ1 = pb1[66];

    float mm = fmaxf(m0, m1);
    #pragma unroll
    for (int o = 16; o; o >>= 1) mm = fmaxf(mm, __shfl_xor_sync(0xffffffffu, mm, o));
    if (lane == 0) wred[warp] = mm;
    __syncthreads();
    if (tid == 0) {
        float M = wred[0];
        #pragma unroll
        for (int i = 1; i < 16; i++) M = fmaxf(M, wred[i]);
        Msh = M;
    }
    __syncthreads();
    float M = Msh;
    float f0 = __expf(m0 - M), f1 = __expf(m1 - M);
    fsh[tid] = f0; fsh[tid + 512] = f1;
    float t0 = T0*f0, t1 = T1*f1;
    float Tl = t0 + t1;
    float P0 = t0*(float)(tid >> 2) + t1*(float)((tid + 512) >> 2);  // row = chunk>>2
    float P1 = PJ0*f0 + PJ1*f1;
    #pragma unroll
    for (int o = 16; o; o >>= 1) {
        Tl += __shfl_xor_sync(0xffffffffu, Tl, o);
        P0 += __shfl_xor_sync(0xffffffffu, P0, o);
        P1 += __shfl_xor_sync(0xffffffffu, P1, o);
    }
    if (lane == 0) { wsum[warp][0] = Tl; wsum[warp][1] = P0; wsum[warp][2] = P1; }
    __syncthreads();
    float Tsh = 0.f, P0sh = 0.f, P1sh = 0.f;
    #pragma unroll
    for (int i = 0; i < 16; i++) { Tsh += wsum[i][0]; P0sh += wsum[i][1]; P1sh += wsum[i][2]; }

    // S-merge: thread = (seg 0..7, c 0..63); each seg covers 128 chunks
    {
        int c = tid & 63, seg = tid >> 6;
        float sacc = 0.f;
        const float* pbase = g_part + (base + (size_t)(seg*128)*NH_ + h)*PST + c;
        #pragma unroll 8
        for (int i = 0; i < 128; i++)
            sacc += pbase[(size_t)i*NH_*PST] * fsh[seg*128 + i];
        Sp[seg][c] = sacc;
    }
    __syncthreads();
    if (tid < 64) {
        float s = 0.f;
        #pragma unroll
        for (int j = 0; j < 8; j++) s += Sp[j][tid];
        Ssh[tid] = s / Tsh;
    }
    __syncthreads();

    if (tid < 256) {
        int e = tid;
        float acc = bv[e];
        const float4* wv = reinterpret_cast<const float4*>(Wv + e*C_);
        const float4* ss = reinterpret_cast<const float4*>(Ssh);
        #pragma unroll
        for (int c2 = 0; c2 < 16; c2++) {
            float4 w = __ldg(wv + c2), sv = ss[c2];
            acc += w.x*sv.x + w.y*sv.y + w.z*sv.z + w.w*sv.w;
        }
        out[(size_t)(b*NH_+h)*E_ + e] = acc;
    }
    if (tid == 0) {
        float invT = 1.f/Tsh;
        out[B_*NH_*E_ + (b*NH_+h)*2]     = P0sh*invT;
        out[B_*NH_*E_ + (b*NH_+h)*2 + 1] = P1sh*invT;
    }
}

extern "C" void kernel_launch(void* const* d_in, const int* in_sizes, int n_in,
                              void* d_out, int out_size)
{
    const float* x   = (const float*)d_in[0];
    const float* z   = (const float*)d_in[1];
    const float* pos = (const float*)d_in[2];
    const float* Wq  = (const float*)d_in[3];
    const float* bq  = (const float*)d_in[4];
    const float* Wk  = (const float*)d_in[5];
    const float* bk  = (const float*)d_in[6];
    const float* Wv  = (const float*)d_in[7];
    const float* bv  = (const float*)d_in[8];
    const float* Wp  = (const float*)d_in[9];
    const float* bp  = (const float*)d_in[10];
    float* out = (float*)d_out;

    cudaFuncSetAttribute(main_kernel, cudaFuncAttributeMaxDynamicSharedMemorySize,
                         SMEM_MAIN_B);

    prep_kernel<<<B_*NH_, 256>>>(z, pos, Wq, bq, Wk, bk, Wp, bp);
    main_kernel<<<dim3(CHB/2, B_), 64, SMEM_MAIN_B>>>(x);
    combine_kernel<<<B_*NH_, 512>>>(Wv, bv, out);
}

// round 11
// speedup vs baseline: 1.1214x; 1.1214x over previous
#include <cuda_runtime.h>

#define B_ 8
#define C_ 64
#define H_ 256
#define W_ 256
#define E_ 256
#define NH_ 8
#define HD_ 32
#define NPIX (H_*W_)

#define TPH 128                  // pixels per half-tile
#define CHB 1024                 // 64-px chunks per batch image
#define PST 68                   // floats per (chunk,head): S[64], m, T, PJ, pad

// smem floats: xs[128*64] | la[128*12] | w8[64*16] | red(96+16) | srow/sbv(16)
#define XS_F (TPH*64)
#define LA_F (TPH*12)
#define W8_F (64*16)
#define SMEM_FLOATS (XS_F + LA_F + W8_F + 112 + 16)

__device__ float g_wa[B_*NH_*C_];
__device__ float g_wb[B_*NH_*C_];
__device__ float g_wc[B_*NH_*C_];
__device__ float g_s [B_*NH_*3];
__device__ float g_part[(size_t)B_*CHB*NH_*PST];

#define FMA2(a, x, w) asm("fma.rn.f32x2 %0, %1, %2, %0;" : "+l"(a) : "l"(x), "l"(w))

// ---------------------------------------------------------------------------
// Prep
// ---------------------------------------------------------------------------
__global__ void prep_kernel(const float* __restrict__ z,  const float* __restrict__ pos,
                            const float* __restrict__ Wq, const float* __restrict__ bq,
                            const float* __restrict__ Wk, const float* __restrict__ bk,
                            const float* __restrict__ Wp, const float* __restrict__ bp)
{
    int b = blockIdx.x >> 3, h = blockIdx.x & 7;
    __shared__ float tA[HD_], tB[HD_], tC[HD_];
    int tid = threadIdx.x;
    const float s = 0.1767766952966369f;  // 1/sqrt(32)

    int c2 = tid >> 2, sub = tid & 3;
    float wkr[8];
    #pragma unroll
    for (int d = 0; d < 8; d++)
        wkr[d] = __ldg(Wk + (h*HD_ + sub*8 + d)*C_ + c2);

    {
        int d = tid >> 3, q = tid & 7;
        int e = h*HD_ + d;
        const float4* zr = reinterpret_cast<const float4*>(z + b*C_);
        const float4* wq = reinterpret_cast<const float4*>(Wq + e*C_);
        float4 z0 = zr[q*2], z1 = zr[q*2+1];
        float4 w0 = __ldg(wq + q*2), w1 = __ldg(wq + q*2 + 1);
        float qv = z0.x*w0.x + z0.y*w0.y + z0.z*w0.z + z0.w*w0.w
                 + z1.x*w1.x + z1.y*w1.y + z1.z*w1.z + z1.w*w1.w;
        qv += __shfl_xor_sync(0xffffffffu, qv, 1);
        qv += __shfl_xor_sync(0xffffffffu, qv, 2);
        qv += __shfl_xor_sync(0xffffffffu, qv, 4);
        if (q == 0) {
            qv += bq[e];
            float wp0 = Wp[2*d], wp1 = Wp[2*d+1];
            float p0 = pos[(b*NH_+h)*2], p1 = pos[(b*NH_+h)*2+1];
            float cc = bp[d] - wp0*p0 - wp1*p1;
            tA[d] = qv*wp0*s; tB[d] = qv*wp1*s; tC[d] = qv*cc*s;
        }
    }
    __syncthreads();
    {
        float a = 0.f, bb = 0.f, cc = 0.f;
        #pragma unroll
        for (int d = 0; d < 8; d++) {
            int dd = sub*8 + d;
            float w = wkr[d];
            a += tA[dd]*w; bb += tB[dd]*w; cc += tC[dd]*w;
        }
        a  += __shfl_xor_sync(0xffffffffu, a, 1);
        bb += __shfl_xor_sync(0xffffffffu, bb, 1);
        cc += __shfl_xor_sync(0xffffffffu, cc, 1);
        a  += __shfl_xor_sync(0xffffffffu, a, 2);
        bb += __shfl_xor_sync(0xffffffffu, bb, 2);
        cc += __shfl_xor_sync(0xffffffffu, cc, 2);
        if (sub == 0) {
            int base = (b*NH_+h)*C_;
            g_wa[base+c2] = a; g_wb[base+c2] = bb; g_wc[base+c2] = cc;
        }
    }
    if (tid < 3) {
        const float* t = (tid==0) ? tA : ((tid==1) ? tB : tC);
        float sv = 0.f;
        #pragma unroll
        for (int d = 0; d < HD_; d++) sv += t[d]*bk[h*HD_ + d];
        g_s[(b*NH_+h)*3 + tid] = sv;
    }
}

// ---------------------------------------------------------------------------
// Main: block = full row (w8 amortized once), processed as 2 halves of 128 px
// through one 32KB xs buffer -> 43.5KB smem, occ 5 (20 warps/SM).
// xs swizzle: word(p,c) = p*64 + ((c + 8*(p&3) + (p>>2)) & 63)
// Each 64-px quarter is an independent softmax chunk (merged in combine).
// ---------------------------------------------------------------------------
__global__ void __launch_bounds__(128, 5) main_kernel(const float* __restrict__ x)
{
    extern __shared__ float sm[];
    float* xs     = sm;                   // [128*64]
    float* la     = xs + XS_F;            // [128][12]
    float* w8     = la + LA_F;            // [64][16]
    float* red_m  = w8 + W8_F;            // [32]
    float* red_t  = red_m + 32;           // [32]
    float* red_pj = red_t + 32;           // [32]
    float* mfin   = red_pj + 32;          // [16] (2 chunks x 8 heads)
    float* srow   = mfin + 16;            // [8]
    float* sbv    = srow + 8;             // [8]

    int row = blockIdx.x, b = blockIdx.y;
    int tid = threadIdx.x;
    int warp = tid >> 5, lane = tid & 31;
    float rowf = (float)row;

    // per-row combined weights, once per block
    if (tid < 64) {
        int c = tid;
        #pragma unroll
        for (int h = 0; h < 8; h++) {
            int gi = (b*NH_+h)*C_ + c;
            w8[c*16 + 2*h]     = g_wc[gi] + rowf*g_wa[gi];
            w8[c*16 + 2*h + 1] = g_wb[gi];
        }
    } else if (tid < 72) {
        int h = tid - 64;
        srow[h] = g_s[(b*NH_+h)*3+2] + rowf*g_s[(b*NH_+h)*3+0];
        sbv[h]  = g_s[(b*NH_+h)*3+1];
    }

    const float* xg0 = x + (size_t)b*C_*NPIX + (size_t)row*W_;

    #pragma unroll 1
    for (int half = 0; half < 2; half++) {
        // ---- stage half: 16 LDG.128/thread in 2 batches of 8, swizzled STS
        {
            const float* xg = xg0 + half*TPH;
            #pragma unroll
            for (int r = 0; r < 2; r++) {
                float4 v[8];
                #pragma unroll
                for (int j = 0; j < 8; j++) {
                    int idx = tid + (r*8 + j)*128;   // 0..2047
                    int c = idx >> 5, q = idx & 31;
                    v[j] = __ldg(reinterpret_cast<const float4*>(xg + (size_t)c*NPIX) + q);
                }
                #pragma unroll
                for (int j = 0; j < 8; j++) {
                    int idx = tid + (r*8 + j)*128;
                    int c = idx >> 5, q = idx & 31;
                    int base = q*4*64;
                    xs[base       + ((c + q     ) & 63)] = v[j].x;
                    xs[base + 64  + ((c + q +  8) & 63)] = v[j].y;
                    xs[base + 128 + ((c + q + 16) & 63)] = v[j].z;
                    xs[base + 192 + ((c + q + 24) & 63)] = v[j].w;
                }
            }
        }
        __syncthreads();   // xs (and, on half 0, w8/srow) ready

        // ---- Phase A: logits, pixel p = tid
        int p = tid;
        float cf = (float)(half*TPH + p);
        float lg[8];
        {
            unsigned long long acc[8];
            #pragma unroll
            for (int h = 0; h < 8; h++) acc[h] = 0ULL;
            const float* xr = xs + p*64;
            int G = 8*(p&3) + (p>>2);
            #pragma unroll 4
            for (int c = 0; c < 64; c++) {
                float xv = xr[(c + G) & 63];
                unsigned long long xx;
                asm("mov.b64 %0, {%1, %1};" : "=l"(xx) : "f"(xv));
                const ulonglong2* wp = reinterpret_cast<const ulonglong2*>(w8 + c*16);
                ulonglong2 wA = wp[0], wB = wp[1];
                FMA2(acc[0], xx, wA.x);
                FMA2(acc[1], xx, wA.y);
                FMA2(acc[2], xx, wB.x);
                FMA2(acc[3], xx, wB.y);
                ulonglong2 wC = wp[2], wD = wp[3];
                FMA2(acc[4], xx, wC.x);
                FMA2(acc[5], xx, wC.y);
                FMA2(acc[6], xx, wD.x);
                FMA2(acc[7], xx, wD.y);
            }
            #pragma unroll
            for (int h = 0; h < 8; h++) {
                float r, bb;
                asm("mov.b64 {%0, %1}, %2;" : "=f"(r), "=f"(bb) : "l"(acc[h]));
                lg[h] = (r + srow[h]) + cf*(bb + sbv[h]);
            }
        }

        // ---- softmax partials per 64-px chunk (warp pair)
        {
            float mh[8];
            #pragma unroll
            for (int h = 0; h < 8; h++) mh[h] = lg[h];
            #pragma unroll
            for (int o = 16; o; o >>= 1) {
                #pragma unroll
                for (int h = 0; h < 8; h++)
                    mh[h] = fmaxf(mh[h], __shfl_xor_sync(0xffffffffu, mh[h], o));
            }
            if (lane == 0) {
                #pragma unroll
                for (int h = 0; h < 8; h++) red_m[warp*8 + h] = mh[h];
            }
            __syncthreads();
            if (tid < 16) {
                int ck = tid >> 3, h = tid & 7;
                mfin[tid] = fmaxf(red_m[(2*ck)*8 + h], red_m[(2*ck+1)*8 + h]);
            }
            __syncthreads();

            int ckl = tid >> 6;   // local chunk 0/1
            float e[8], th[8], pjh[8];
            #pragma unroll
            for (int h = 0; h < 8; h++) {
                e[h] = __expf(lg[h] - mfin[ckl*8 + h]);
                th[h]  = e[h];
                pjh[h] = e[h]*cf;
            }
            *reinterpret_cast<float4*>(la + p*12)     = make_float4(e[0], e[1], e[2], e[3]);
            *reinterpret_cast<float4*>(la + p*12 + 4) = make_float4(e[4], e[5], e[6], e[7]);
            #pragma unroll
            for (int o = 16; o; o >>= 1) {
                #pragma unroll
                for (int h = 0; h < 8; h++) {
                    th[h]  += __shfl_xor_sync(0xffffffffu, th[h],  o);
                    pjh[h] += __shfl_xor_sync(0xffffffffu, pjh[h], o);
                }
            }
            if (lane == 0) {
                #pragma unroll
                for (int h = 0; h < 8; h++) {
                    red_t[warp*8 + h]  = th[h];
                    red_pj[warp*8 + h] = pjh[h];
                }
            }
            __syncthreads();   // la + red_t/red_pj ready
            if (tid < 16) {
                int ck = tid >> 3, h = tid & 7;
                float T  = red_t[(2*ck)*8 + h]  + red_t[(2*ck+1)*8 + h];
                float PJ = red_pj[(2*ck)*8 + h] + red_pj[(2*ck+1)*8 + h];
                size_t pb = ((size_t)(b*CHB + row*4 + half*2 + ck)*NH_ + h)*PST;
                g_part[pb + 64] = mfin[tid];
                g_part[pb + 65] = T;
                g_part[pb + 66] = PJ;
            }
        }

        // ---- Phase B: group g (64 threads) owns chunk (64 px); c = tid&63
        {
            int c = tid & 63, g = tid >> 6;
            unsigned long long acc[4];
            #pragma unroll
            for (int j = 0; j < 4; j++) acc[j] = 0ULL;
            int pbase = g*64;
            #pragma unroll 4
            for (int i = 0; i < 64; i++) {
                int pp = pbase + i;
                int col = (c + 8*(pp&3) + (pp>>2)) & 63;
                float xv = xs[pp*64 + col];
                unsigned long long xx;
                asm("mov.b64 %0, {%1, %1};" : "=l"(xx) : "f"(xv));
                ulonglong2 eA = *reinterpret_cast<const ulonglong2*>(la + pp*12);
                ulonglong2 eB = *reinterpret_cast<const ulonglong2*>(la + pp*12 + 4);
                FMA2(acc[0], xx, eA.x);
                FMA2(acc[1], xx, eA.y);
                FMA2(acc[2], xx, eB.x);
                FMA2(acc[3], xx, eB.y);
            }
            size_t cb = (size_t)(b*CHB + row*4 + half*2 + g)*NH_;
            #pragma unroll
            for (int j = 0; j < 4; j++) {
                float lo, hi;
                asm("mov.b64 {%0, %1}, %2;" : "=f"(lo), "=f"(hi) : "l"(acc[j]));
                g_part[(cb + 2*j    )*PST + c] = lo;
                g_part[(cb + 2*j + 1)*PST + c] = hi;
            }
        }
        __syncthreads();   // xs/la reads done before next half overwrites
    }
}

// ---------------------------------------------------------------------------
// Combine: per (b,h), 512 threads merge 1024 chunk-partials (L2-resident).
// ---------------------------------------------------------------------------
__global__ void __launch_bounds__(512) combine_kernel(const float* __restrict__ Wv,
                                                      const float* __restrict__ bv,
                                                      float* __restrict__ out)
{
    int b = blockIdx.x >> 3, h = blockIdx.x & 7;
    __shared__ float fsh[CHB], Ssh[64], Sp[8][64];
    __shared__ float wred[16], wsum[16][3];
    __shared__ float Msh;
    int tid = threadIdx.x, warp = tid >> 5, lane = tid & 31;

    size_t base = (size_t)b*CHB*NH_;
    const float* pb0 = g_part + (base + (size_t)tid*NH_ + h)*PST;
    const float* pb1 = g_part + (base + (size_t)(tid+512)*NH_ + h)*PST;
    float m0 = pb0[64], T0 = pb0[65], PJ0 = pb0[66];
    float m1 = pb1[64], T1 = pb1[65], PJ1 = pb1[66];

    float mm = fmaxf(m0, m1);
    #pragma unroll
    for (int o = 16; o; o >>= 1) mm = fmaxf(mm, __shfl_xor_sync(0xffffffffu, mm, o));
    if (lane == 0) wred[warp] = mm;
    __syncthreads();
    if (tid == 0) {
        float M = wred[0];
        #pragma unroll
        for (int i = 1; i < 16; i++) M = fmaxf(M, wred[i]);
        Msh = M;
    }
    __syncthreads();
    float M = Msh;
    float f0 = __expf(m0 - M), f1 = __expf(m1 - M);
    fsh[tid] = f0; fsh[tid + 512] = f1;
    float t0 = T0*f0, t1 = T1*f1;
    float Tl = t0 + t1;
    float P0 = t0*(float)(tid >> 2) + t1*(float)((tid + 512) >> 2);  // row = chunk>>2
    float P1 = PJ0*f0 + PJ1*f1;
    #pragma unroll
    for (int o = 16; o; o >>= 1) {
        Tl += __shfl_xor_sync(0xffffffffu, Tl, o);
        P0 += __shfl_xor_sync(0xffffffffu, P0, o);
        P1 += __shfl_xor_sync(0xffffffffu, P1, o);
    }
    if (lane == 0) { wsum[warp][0] = Tl; wsum[warp][1] = P0; wsum[warp][2] = P1; }
    __syncthreads();
    float Tsh = 0.f, P0sh = 0.f, P1sh = 0.f;
    #pragma unroll
    for (int i = 0; i < 16; i++) { Tsh += wsum[i][0]; P0sh += wsum[i][1]; P1sh += wsum[i][2]; }

    {
        int c = tid & 63, seg = tid >> 6;
        float sacc = 0.f;
        const float* pbase = g_part + (base + (size_t)(seg*128)*NH_ + h)*PST + c;
        #pragma unroll 8
        for (int i = 0; i < 128; i++)
            sacc += pbase[(size_t)i*NH_*PST] * fsh[seg*128 + i];
        Sp[seg][c] = sacc;
    }
    __syncthreads();
    if (tid < 64) {
        float s = 0.f;
        #pragma unroll
        for (int j = 0; j < 8; j++) s += Sp[j][tid];
        Ssh[tid] = s / Tsh;
    }
    __syncthreads();

    if (tid < 256) {
        int e = tid;
        float acc = bv[e];
        const float4* wv = reinterpret_cast<const float4*>(Wv + e*C_);
        const float4* ss = reinterpret_cast<const float4*>(Ssh);
        #pragma unroll
        for (int c2 = 0; c2 < 16; c2++) {
            float4 w = __ldg(wv + c2), sv = ss[c2];
            acc += w.x*sv.x + w.y*sv.y + w.z*sv.z + w.w*sv.w;
        }
        out[(size_t)(b*NH_+h)*E_ + e] = acc;
    }
    if (tid == 0) {
        float invT = 1.f/Tsh;
        out[B_*NH_*E_ + (b*NH_+h)*2]     = P0sh*invT;
        out[B_*NH_*E_ + (b*NH_+h)*2 + 1] = P1sh*invT;
    }
}

extern "C" void kernel_launch(void* const* d_in, const int* in_sizes, int n_in,
                              void* d_out, int out_size)
{
    const float* x   = (const float*)d_in[0];
    const float* z   = (const float*)d_in[1];
    const float* pos = (const float*)d_in[2];
    const float* Wq  = (const float*)d_in[3];
    const float* bq  = (const float*)d_in[4];
    const float* Wk  = (const float*)d_in[5];
    const float* bk  = (const float*)d_in[6];
    const float* Wv  = (const float*)d_in[7];
    const float* bv  = (const float*)d_in[8];
    const float* Wp  = (const float*)d_in[9];
    const float* bp  = (const float*)d_in[10];
    float* out = (float*)d_out;

    cudaFuncSetAttribute(main_kernel, cudaFuncAttributeMaxDynamicSharedMemorySize,
                         SMEM_FLOATS * (int)sizeof(float));

    prep_kernel<<<B_*NH_, 256>>>(z, pos, Wq, bq, Wk, bk, Wp, bp);
    main_kernel<<<dim3(H_, B_), 128, SMEM_FLOATS * sizeof(float)>>>(x);
    combine_kernel<<<B_*NH_, 512>>>(Wv, bv, out);
}

// round 12
// speedup vs baseline: 1.1218x; 1.0003x over previous
#include <cuda_runtime.h>

#define B_ 8
#define C_ 64
#define H_ 256
#define W_ 256
#define E_ 256
#define NH_ 8
#define HD_ 32
#define NPIX (H_*W_)

// smem floats: xs[64*256 quad layout] | la[256*12] | w8[64*16] | red[104] | srow/sbv[16]
#define XS_F   (256*64)
#define LA_F   (256*12)
#define W8_F   (64*16)
#define RED_F  104
#define SMEM_FLOATS (XS_F + LA_F + W8_F + RED_F + 16)

__device__ float g_wa[B_*NH_*C_];
__device__ float g_wb[B_*NH_*C_];
__device__ float g_wc[B_*NH_*C_];
__device__ float g_s [B_*NH_*3];
__device__ float g_part[(size_t)B_*H_*NH_*68];   // per (b,row,h): S[64], m, T, PJ, pad

#define FMA2(a, x, w) asm("fma.rn.f32x2 %0, %1, %2, %0;" : "+l"(a) : "l"(x), "l"(w))

#define CP_ASYNC16(dst, src) \
    asm volatile("cp.async.cg.shared.global [%0], [%1], 16;" :: "r"(dst), "l"(src) : "memory")
#define CP_COMMIT() asm volatile("cp.async.commit_group;" ::: "memory")
#define CP_WAIT(n)  asm volatile("cp.async.wait_group %0;" :: "n"(n) : "memory")

// ---------------------------------------------------------------------------
// Prep: per (b,h) build wa/wb/wc[64] and scalars. (unchanged from r5/r11)
// ---------------------------------------------------------------------------
__global__ void prep_kernel(const float* __restrict__ z,  const float* __restrict__ pos,
                            const float* __restrict__ Wq, const float* __restrict__ bq,
                            const float* __restrict__ Wk, const float* __restrict__ bk,
                            const float* __restrict__ Wp, const float* __restrict__ bp)
{
    int b = blockIdx.x >> 3, h = blockIdx.x & 7;
    __shared__ float tA[HD_], tB[HD_], tC[HD_];
    int tid = threadIdx.x;
    const float s = 0.1767766952966369f;  // 1/sqrt(32)

    int c2 = tid >> 2, sub = tid & 3;
    float wkr[8];
    #pragma unroll
    for (int d = 0; d < 8; d++)
        wkr[d] = __ldg(Wk + (h*HD_ + sub*8 + d)*C_ + c2);

    {
        int d = tid >> 3, q = tid & 7;
        int e = h*HD_ + d;
        const float4* zr = reinterpret_cast<const float4*>(z + b*C_);
        const float4* wq = reinterpret_cast<const float4*>(Wq + e*C_);
        float4 z0 = zr[q*2], z1 = zr[q*2+1];
        float4 w0 = __ldg(wq + q*2), w1 = __ldg(wq + q*2 + 1);
        float qv = z0.x*w0.x + z0.y*w0.y + z0.z*w0.z + z0.w*w0.w
                 + z1.x*w1.x + z1.y*w1.y + z1.z*w1.z + z1.w*w1.w;
        qv += __shfl_xor_sync(0xffffffffu, qv, 1);
        qv += __shfl_xor_sync(0xffffffffu, qv, 2);
        qv += __shfl_xor_sync(0xffffffffu, qv, 4);
        if (q == 0) {
            qv += bq[e];
            float wp0 = Wp[2*d], wp1 = Wp[2*d+1];
            float p0 = pos[(b*NH_+h)*2], p1 = pos[(b*NH_+h)*2+1];
            float cc = bp[d] - wp0*p0 - wp1*p1;
            tA[d] = qv*wp0*s; tB[d] = qv*wp1*s; tC[d] = qv*cc*s;
        }
    }
    __syncthreads();
    {
        float a = 0.f, bb = 0.f, cc = 0.f;
        #pragma unroll
        for (int d = 0; d < 8; d++) {
            int dd = sub*8 + d;
            float w = wkr[d];
            a += tA[dd]*w; bb += tB[dd]*w; cc += tC[dd]*w;
        }
        a  += __shfl_xor_sync(0xffffffffu, a, 1);
        bb += __shfl_xor_sync(0xffffffffu, bb, 1);
        cc += __shfl_xor_sync(0xffffffffu, cc, 1);
        a  += __shfl_xor_sync(0xffffffffu, a, 2);
        bb += __shfl_xor_sync(0xffffffffu, bb, 2);
        cc += __shfl_xor_sync(0xffffffffu, cc, 2);
        if (sub == 0) {
            int base = (b*NH_+h)*C_;
            g_wa[base+c2] = a; g_wb[base+c2] = bb; g_wc[base+c2] = cc;
        }
    }
    if (tid < 3) {
        const float* t = (tid==0) ? tA : ((tid==1) ? tB : tC);
        float sv = 0.f;
        #pragma unroll
        for (int d = 0; d < HD_; d++) sv += t[d]*bk[h*HD_ + d];
        g_s[(b*NH_+h)*3 + tid] = sv;
    }
}

// ---------------------------------------------------------------------------
// Main: one block per (b, row), 128 threads, occ 2 (r5 economics), but staging
// is cp.async channel-pipelined: c[0:32) computes while c[32:64) streams.
// xs quad layout: x[p][c] at xs[(p>>2)*256 + ((c + (p>>2)) & 63)*4 + (p&3)]
//   - staging LDGSTS.128: 16B contiguous dst, optimal phases
//   - phase A scalar reads (lanes=pixel): conflict-free
//   - phase B LDS.128 quad reads (lanes=channel): 4 phases/512B (optimal)
// ---------------------------------------------------------------------------
__global__ void __launch_bounds__(128, 2) main_kernel(const float* __restrict__ x)
{
    extern __shared__ float sm[];
    float* xs   = sm;                      // [64 quads][64 c][4 px]
    float* la   = sm + XS_F;               // [256][12]
    float* w8   = la + LA_F;               // [64][16]; reused as Sp in phase B
    float* red  = w8 + W8_F;
    float* srow = red + RED_F;
    float* sbv  = srow + 8;
    float* red_m = red, *red_t = red + 32, *red_pj = red + 64, *mfin = red + 96;

    int row = blockIdx.x, b = blockIdx.y;
    int tid = threadIdx.x;
    int warp = tid >> 5, lane = tid & 31;

    unsigned xs_u32 = (unsigned)__cvta_generic_to_shared(xs);
    const float* xg = x + (size_t)b*C_*NPIX + (size_t)row*W_;

    // ---- async stage: two channel-halves, 16 LDGSTS.128/thread each
    #pragma unroll
    for (int ch = 0; ch < 2; ch++) {
        #pragma unroll
        for (int k = 0; k < 16; k++) {
            int idx = tid + k*128;           // 0..2047
            int cl = idx >> 6, q = idx & 63;
            int c = ch*32 + cl;
            const float* src = xg + (size_t)c*NPIX + q*4;
            unsigned dst = xs_u32 + (q*256 + ((c + q) & 63)*4)*4;
            CP_ASYNC16(dst, src);
        }
        CP_COMMIT();
    }

    // per-row combined weights (sync loads, overlap with async copies)
    if (tid < 64) {
        int c = tid;
        float rf = (float)row;
        #pragma unroll
        for (int h = 0; h < 8; h++) {
            int gi = (b*NH_+h)*C_ + c;
            w8[c*16 + 2*h]     = g_wc[gi] + rf*g_wa[gi];
            w8[c*16 + 2*h + 1] = g_wb[gi];
        }
    } else if (tid < 72) {
        int h = tid - 64;
        srow[h] = g_s[(b*NH_+h)*3+2] + (float)row*g_s[(b*NH_+h)*3+0];
        sbv[h]  = g_s[(b*NH_+h)*3+1];
    }

    // ---- Phase A: logits, 2 pixels per thread (p0=tid, p1=tid+128),
    //      pipelined over the two channel halves.
    int p0 = tid, p1 = tid + 128;
    int q0 = p0 >> 2, q1 = p1 >> 2;
    int base0 = q0*256 + (p0 & 3);
    int base1 = q1*256 + (p1 & 3);
    float l0[8], l1[8];
    unsigned long long acc0[8], acc1[8];
    #pragma unroll
    for (int h = 0; h < 8; h++) { acc0[h] = 0ULL; acc1[h] = 0ULL; }

    CP_WAIT(1);          // first channel-half landed
    __syncthreads();     // (also fences w8/srow)

    #pragma unroll 1
    for (int ch = 0; ch < 2; ch++) {
        int cbase = ch*32;
        #pragma unroll 4
        for (int cl = 0; cl < 32; cl++) {
            int c = cbase + cl;
            float x0 = xs[base0 + ((c + q0) & 63)*4];
            float x1 = xs[base1 + ((c + q1) & 63)*4];
            unsigned long long xx0, xx1;
            asm("mov.b64 %0, {%1, %1};" : "=l"(xx0) : "f"(x0));
            asm("mov.b64 %0, {%1, %1};" : "=l"(xx1) : "f"(x1));
            const ulonglong2* wp = reinterpret_cast<const ulonglong2*>(w8 + c*16);
            ulonglong2 wA = wp[0], wB = wp[1];
            FMA2(acc0[0], xx0, wA.x);  FMA2(acc1[0], xx1, wA.x);
            FMA2(acc0[1], xx0, wA.y);  FMA2(acc1[1], xx1, wA.y);
            FMA2(acc0[2], xx0, wB.x);  FMA2(acc1[2], xx1, wB.x);
            FMA2(acc0[3], xx0, wB.y);  FMA2(acc1[3], xx1, wB.y);
            ulonglong2 wC = wp[2], wD = wp[3];
            FMA2(acc0[4], xx0, wC.x);  FMA2(acc1[4], xx1, wC.x);
            FMA2(acc0[5], xx0, wC.y);  FMA2(acc1[5], xx1, wC.y);
            FMA2(acc0[6], xx0, wD.x);  FMA2(acc1[6], xx1, wD.x);
            FMA2(acc0[7], xx0, wD.y);  FMA2(acc1[7], xx1, wD.y);
        }
        if (ch == 0) {
            CP_WAIT(0);      // second half landed
            __syncwarp();
        }
    }
    {
        float c0f = (float)p0, c1f = (float)p1;
        #pragma unroll
        for (int h = 0; h < 8; h++) {
            float r, bb;
            asm("mov.b64 {%0, %1}, %2;" : "=f"(r), "=f"(bb) : "l"(acc0[h]));
            l0[h] = (r + srow[h]) + c0f*(bb + sbv[h]);
            asm("mov.b64 {%0, %1}, %2;" : "=f"(r), "=f"(bb) : "l"(acc1[h]));
            l1[h] = (r + srow[h]) + c1f*(bb + sbv[h]);
        }
    }

    // ---- softmax over the row (registers + shuffles; identical to r5)
    {
        float mh[8];
        #pragma unroll
        for (int h = 0; h < 8; h++) mh[h] = fmaxf(l0[h], l1[h]);
        #pragma unroll
        for (int o = 16; o; o >>= 1) {
            #pragma unroll
            for (int h = 0; h < 8; h++)
                mh[h] = fmaxf(mh[h], __shfl_xor_sync(0xffffffffu, mh[h], o));
        }
        if (lane == 0) {
            #pragma unroll
            for (int h = 0; h < 8; h++) red_m[warp*8 + h] = mh[h];
        }
        __syncthreads();
        if (tid < 8)
            mfin[tid] = fmaxf(fmaxf(red_m[tid], red_m[8+tid]),
                              fmaxf(red_m[16+tid], red_m[24+tid]));
        __syncthreads();

        float th[8], pjh[8], e0[8], e1[8];
        float c0f = (float)p0, c1f = (float)p1;
        #pragma unroll
        for (int h = 0; h < 8; h++) {
            float M = mfin[h];
            e0[h] = __expf(l0[h] - M);
            e1[h] = __expf(l1[h] - M);
            th[h]  = e0[h] + e1[h];
            pjh[h] = e0[h]*c0f + e1[h]*c1f;
        }
        *reinterpret_cast<float4*>(la + p0*12)     = make_float4(e0[0], e0[1], e0[2], e0[3]);
        *reinterpret_cast<float4*>(la + p0*12 + 4) = make_float4(e0[4], e0[5], e0[6], e0[7]);
        *reinterpret_cast<float4*>(la + p1*12)     = make_float4(e1[0], e1[1], e1[2], e1[3]);
        *reinterpret_cast<float4*>(la + p1*12 + 4) = make_float4(e1[4], e1[5], e1[6], e1[7]);

        #pragma unroll
        for (int o = 16; o; o >>= 1) {
            #pragma unroll
            for (int h = 0; h < 8; h++) {
                th[h]  += __shfl_xor_sync(0xffffffffu, th[h],  o);
                pjh[h] += __shfl_xor_sync(0xffffffffu, pjh[h], o);
            }
        }
        if (lane == 0) {
            #pragma unroll
            for (int h = 0; h < 8; h++) {
                red_t[warp*8 + h]  = th[h];
                red_pj[warp*8 + h] = pjh[h];
            }
        }
        __syncthreads();
        if (tid < 8) {
            float T  = red_t[tid]  + red_t[8+tid]  + red_t[16+tid]  + red_t[24+tid];
            float PJ = red_pj[tid] + red_pj[8+tid] + red_pj[16+tid] + red_pj[24+tid];
            size_t pb = ((size_t)(b*H_ + row)*NH_ + tid)*68;
            g_part[pb + 64] = mfin[tid];
            g_part[pb + 65] = T;
            g_part[pb + 66] = PJ;
        }
    }

    // ---- Phase B: S[h][c] = sum_p e[p][h]*x[p][c]; quad LDS.128 x-reads
    {
        int c = tid & 63, g = tid >> 6;
        unsigned long long acc[4];
        #pragma unroll
        for (int j = 0; j < 4; j++) acc[j] = 0ULL;
        #pragma unroll 2
        for (int qi = 0; qi < 32; qi++) {
            int q = g*32 + qi;               // pixels 4q..4q+3
            float4 xq = *reinterpret_cast<const float4*>(xs + q*256 + ((c + q) & 63)*4);
            const float* lb = la + (q*4)*12;
            unsigned long long xx;
            ulonglong2 eA, eB;
            asm("mov.b64 %0, {%1, %1};" : "=l"(xx) : "f"(xq.x));
            eA = *reinterpret_cast<const ulonglong2*>(lb);
            eB = *reinterpret_cast<const ulonglong2*>(lb + 4);
            FMA2(acc[0], xx, eA.x); FMA2(acc[1], xx, eA.y);
            FMA2(acc[2], xx, eB.x); FMA2(acc[3], xx, eB.y);
            asm("mov.b64 %0, {%1, %1};" : "=l"(xx) : "f"(xq.y));
            eA = *reinterpret_cast<const ulonglong2*>(lb + 12);
            eB = *reinterpret_cast<const ulonglong2*>(lb + 16);
            FMA2(acc[0], xx, eA.x); FMA2(acc[1], xx, eA.y);
            FMA2(acc[2], xx, eB.x); FMA2(acc[3], xx, eB.y);
            asm("mov.b64 %0, {%1, %1};" : "=l"(xx) : "f"(xq.z));
            eA = *reinterpret_cast<const ulonglong2*>(lb + 24);
            eB = *reinterpret_cast<const ulonglong2*>(lb + 28);
            FMA2(acc[0], xx, eA.x); FMA2(acc[1], xx, eA.y);
            FMA2(acc[2], xx, eB.x); FMA2(acc[3], xx, eB.y);
            asm("mov.b64 %0, {%1, %1};" : "=l"(xx) : "f"(xq.w));
            eA = *reinterpret_cast<const ulonglong2*>(lb + 36);
            eB = *reinterpret_cast<const ulonglong2*>(lb + 40);
            FMA2(acc[0], xx, eA.x); FMA2(acc[1], xx, eA.y);
            FMA2(acc[2], xx, eB.x); FMA2(acc[3], xx, eB.y);
        }
        float* Sp = w8;  // reuse
        __syncthreads();
        *reinterpret_cast<ulonglong2*>(Sp + tid*8)     = make_ulonglong2(acc[0], acc[1]);
        *reinterpret_cast<ulonglong2*>(Sp + tid*8 + 4) = make_ulonglong2(acc[2], acc[3]);
        __syncthreads();
        if (tid < 64) {
            size_t chk = (size_t)(b*H_ + row)*NH_;
            #pragma unroll
            for (int h = 0; h < 8; h++)
                g_part[(chk + h)*68 + tid] = Sp[tid*8 + h] + Sp[(tid+64)*8 + h];
        }
    }
}

// ---------------------------------------------------------------------------
// Combine: per (b,h) rescale 256 row-partials (r5 version).
// ---------------------------------------------------------------------------
__global__ void combine_kernel(const float* __restrict__ Wv, const float* __restrict__ bv,
                               float* __restrict__ out)
{
    int b = blockIdx.x >> 3, h = blockIdx.x & 7;
    __shared__ float fsh[256], Ssh[64], Sp[4][64];
    __shared__ float wred[8], wsum[8][3];
    __shared__ float Msh;
    int tid = threadIdx.x, warp = tid >> 5, lane = tid & 31;

    const float* pb = g_part + ((size_t)(b*H_+tid)*NH_ + h)*68;
    float m = pb[64], T0 = pb[65], PJ0 = pb[66];

    float mm = m;
    #pragma unroll
    for (int o = 16; o; o >>= 1) mm = fmaxf(mm, __shfl_xor_sync(0xffffffffu, mm, o));
    if (lane == 0) wred[warp] = mm;
    __syncthreads();
    if (tid == 0) {
        float M = wred[0];
        #pragma unroll
        for (int i = 1; i < 8; i++) M = fmaxf(M, wred[i]);
        Msh = M;
    }
    __syncthreads();
    float M = Msh;
    float f = __expf(m - M);
    fsh[tid] = f;
    float Tl = T0*f, P0 = Tl*(float)tid, P1 = PJ0*f;
    #pragma unroll
    for (int o = 16; o; o >>= 1) {
        Tl += __shfl_xor_sync(0xffffffffu, Tl, o);
        P0 += __shfl_xor_sync(0xffffffffu, P0, o);
        P1 += __shfl_xor_sync(0xffffffffu, P1, o);
    }
    if (lane == 0) { wsum[warp][0] = Tl; wsum[warp][1] = P0; wsum[warp][2] = P1; }
    __syncthreads();
    float Tsh = 0.f, P0sh = 0.f, P1sh = 0.f;
    #pragma unroll
    for (int i = 0; i < 8; i++) { Tsh += wsum[i][0]; P0sh += wsum[i][1]; P1sh += wsum[i][2]; }

    int c = tid & 63, seg = tid >> 6;
    float sacc = 0.f;
    const float* pbase = g_part + ((size_t)(b*H_ + seg*64)*NH_ + h)*68 + c;
    #pragma unroll 4
    for (int i = 0; i < 64; i++)
        sacc += pbase[(size_t)i*NH_*68] * fsh[seg*64 + i];
    Sp[seg][c] = sacc; __syncthreads();
    if (tid < 64) Ssh[tid] = (Sp[0][tid] + Sp[1][tid] + Sp[2][tid] + Sp[3][tid]) / Tsh;
    __syncthreads();

    int e = tid;
    float acc = bv[e];
    const float4* wv = reinterpret_cast<const float4*>(Wv + e*C_);
    const float4* ss = reinterpret_cast<const float4*>(Ssh);
    #pragma unroll
    for (int c2 = 0; c2 < 16; c2++) {
        float4 w = __ldg(wv + c2), sv = ss[c2];
        acc += w.x*sv.x + w.y*sv.y + w.z*sv.z + w.w*sv.w;
    }
    out[(size_t)(b*NH_+h)*E_ + e] = acc;

    if (tid == 0) {
        float invT = 1.f/Tsh;
        out[B_*NH_*E_ + (b*NH_+h)*2]     = P0sh*invT;
        out[B_*NH_*E_ + (b*NH_+h)*2 + 1] = P1sh*invT;
    }
}

extern "C" void kernel_launch(void* const* d_in, const int* in_sizes, int n_in,
                              void* d_out, int out_size)
{
    const float* x   = (const float*)d_in[0];
    const float* z   = (const float*)d_in[1];
    const float* pos = (const float*)d_in[2];
    const float* Wq  = (const float*)d_in[3];
    const float* bq  = (const float*)d_in[4];
    const float* Wk  = (const float*)d_in[5];
    const float* bk  = (const float*)d_in[6];
    const float* Wv  = (const float*)d_in[7];
    const float* bv  = (const float*)d_in[8];
    const float* Wp  = (const float*)d_in[9];
    const float* bp  = (const float*)d_in[10];
    float* out = (float*)d_out;

    cudaFuncSetAttribute(main_kernel, cudaFuncAttributeMaxDynamicSharedMemorySize,
                         SMEM_FLOATS * (int)sizeof(float));

    prep_kernel<<<B_*NH_, 256>>>(z, pos, Wq, bq, Wk, bk, Wp, bp);
    main_kernel<<<dim3(H_, B_), 128, SMEM_FLOATS * sizeof(float)>>>(x);
    combine_kernel<<<B_*NH_, 256>>>(Wv, bv, out);
}